// round 2
// baseline (speedup 1.0000x reference)
#include <cuda_runtime.h>

#define MAXN 100000

// ---------------- scratch (device globals; no allocations allowed) ----------
__device__ __align__(16) float    g_h1[MAXN * 128];
__device__ __align__(16) float    g_as1[MAXN * 4];
__device__ __align__(16) float    g_ad1[MAXN * 4];
__device__ unsigned               g_emax1[MAXN * 4];
__device__ float                  g_denom1[MAXN * 4];
__device__ __align__(16) float    g_numer1[MAXN * 128];
__device__ float                  g_h2[MAXN];
__device__ unsigned               g_emax2[MAXN];
__device__ float                  g_denom2[MAXN];
__device__ float                  g_numer2[MAXN];
__device__ int                    g_is64;

// order-preserving float <-> unsigned encoding (for atomicMax on floats)
__device__ __forceinline__ unsigned fenc(float f) {
    unsigned u = __float_as_uint(f);
    return (u & 0x80000000u) ? ~u : (u | 0x80000000u);
}
__device__ __forceinline__ float fdec(unsigned u) {
    return (u & 0x80000000u) ? __uint_as_float(u ^ 0x80000000u)
                             : __uint_as_float(~u);
}

__device__ __forceinline__ float lrelu(float v) { return v > 0.f ? v : 0.2f * v; }

// Edge fetch that works for both int32 and int64 edge_index layouts.
__device__ __forceinline__ void edge_fetch(const void* ei, int e_cnt, int i,
                                           int is64, int& src, int& dst) {
    if (is64) {
        const long long* p = (const long long*)ei;
        src = (int)p[i];
        dst = (int)p[e_cnt + i];
    } else {
        const int* p = (const int*)ei;
        src = p[i];
        dst = p[e_cnt + i];
    }
}

// ---------------- dtype detection: int64 iff all sampled high-words are 0 ---
__global__ void detect_kernel(const unsigned* __restrict__ ei_u32, int e_cnt) {
    __shared__ int bad;
    if (threadIdx.x == 0) bad = 0;
    __syncthreads();
    int samples = e_cnt < 4096 ? e_cnt : 4096;
    // interpret as int64 words: word i has high half at u32 index 2*i+1
    for (int i = threadIdx.x; i < samples; i += blockDim.x) {
        if (ei_u32[2 * i + 1] != 0u) bad = 1;
    }
    __syncthreads();
    if (threadIdx.x == 0) g_is64 = bad ? 0 : 1;
}

// ---------------- GEMM1: h1 = x @ W1  ([n,128] x [128,128]) -----------------
// Block: 256 threads, 64 rows x 128 cols per block. Full W1 + X-tile in smem.
__global__ void gemm1_kernel(const float* __restrict__ x,
                             const float* __restrict__ W, int n) {
    extern __shared__ float sm[];
    float4* Ws4 = (float4*)sm;                 // 128*128 floats = 4096 float4
    float4* Xs4 = (float4*)(sm + 128 * 128);   // 64*128 floats  = 2048 float4
    int t = threadIdx.x;

    const float4* Wg4 = (const float4*)W;
#pragma unroll
    for (int i = 0; i < 16; i++) Ws4[t + i * 256] = Wg4[t + i * 256];

    int row0 = blockIdx.x * 64;
    const float4* Xg4 = (const float4*)x;
#pragma unroll
    for (int i = 0; i < 8; i++) {
        int idx = t + i * 256;          // 0..2047
        int r = idx >> 5;
        float4 v = make_float4(0.f, 0.f, 0.f, 0.f);
        if (row0 + r < n) v = Xg4[(row0 + r) * 32 + (idx & 31)];
        Xs4[idx] = v;
    }
    __syncthreads();

    int cg = t & 31;   // col group: cols cg*4 .. cg*4+3
    int rg = t >> 5;   // row group: rows rg*8 .. rg*8+7
    float4 acc[8];
#pragma unroll
    for (int j = 0; j < 8; j++) acc[j] = make_float4(0.f, 0.f, 0.f, 0.f);

    for (int k = 0; k < 128; k += 4) {
        float4 b0 = Ws4[(k + 0) * 32 + cg];
        float4 b1 = Ws4[(k + 1) * 32 + cg];
        float4 b2 = Ws4[(k + 2) * 32 + cg];
        float4 b3 = Ws4[(k + 3) * 32 + cg];
#pragma unroll
        for (int j = 0; j < 8; j++) {
            float4 a = Xs4[(rg * 8 + j) * 32 + (k >> 2)];
            acc[j].x += a.x * b0.x + a.y * b1.x + a.z * b2.x + a.w * b3.x;
            acc[j].y += a.x * b0.y + a.y * b1.y + a.z * b2.y + a.w * b3.y;
            acc[j].z += a.x * b0.z + a.y * b1.z + a.z * b2.z + a.w * b3.z;
            acc[j].w += a.x * b0.w + a.y * b1.w + a.z * b2.w + a.w * b3.w;
        }
    }

    float4* Hg4 = (float4*)g_h1;
#pragma unroll
    for (int j = 0; j < 8; j++) {
        int r = row0 + rg * 8 + j;
        if (r < n) Hg4[r * 32 + cg] = acc[j];
    }
}

// ---------------- attention coefficients: a_s, a_d (warp per node) ----------
__global__ void att1_kernel(const float* __restrict__ att_src,
                            const float* __restrict__ att_dst, int n) {
    int warp = (blockIdx.x * blockDim.x + threadIdx.x) >> 5;
    int lane = threadIdx.x & 31;
    if (warp >= n) return;
    float s0, s1, s2, s3, d0, d1, d2, d3;
    {
        float h0 = g_h1[warp * 128 + 0 * 32 + lane];
        float h1 = g_h1[warp * 128 + 1 * 32 + lane];
        float h2 = g_h1[warp * 128 + 2 * 32 + lane];
        float h3 = g_h1[warp * 128 + 3 * 32 + lane];
        s0 = h0 * att_src[0 * 32 + lane]; d0 = h0 * att_dst[0 * 32 + lane];
        s1 = h1 * att_src[1 * 32 + lane]; d1 = h1 * att_dst[1 * 32 + lane];
        s2 = h2 * att_src[2 * 32 + lane]; d2 = h2 * att_dst[2 * 32 + lane];
        s3 = h3 * att_src[3 * 32 + lane]; d3 = h3 * att_dst[3 * 32 + lane];
    }
#pragma unroll
    for (int o = 16; o > 0; o >>= 1) {
        s0 += __shfl_xor_sync(0xffffffffu, s0, o);
        s1 += __shfl_xor_sync(0xffffffffu, s1, o);
        s2 += __shfl_xor_sync(0xffffffffu, s2, o);
        s3 += __shfl_xor_sync(0xffffffffu, s3, o);
        d0 += __shfl_xor_sync(0xffffffffu, d0, o);
        d1 += __shfl_xor_sync(0xffffffffu, d1, o);
        d2 += __shfl_xor_sync(0xffffffffu, d2, o);
        d3 += __shfl_xor_sync(0xffffffffu, d3, o);
    }
    if (lane == 0) {
        ((float4*)g_as1)[warp] = make_float4(s0, s1, s2, s3);
        ((float4*)g_ad1)[warp] = make_float4(d0, d1, d2, d3);
    }
}

// ---------------- layer-1 edge pass A: segment max over dst -----------------
__global__ void edgeA1_kernel(const void* __restrict__ ei, int e_cnt, int n) {
    int i = blockIdx.x * blockDim.x + threadIdx.x;
    int tot = e_cnt + n;
    if (i >= tot) return;
    int is64 = g_is64;
    int src, dst;
    if (i < e_cnt) edge_fetch(ei, e_cnt, i, is64, src, dst);
    else           src = dst = i - e_cnt;
    float4 as = ((const float4*)g_as1)[src];
    float4 ad = ((const float4*)g_ad1)[dst];
    float e0 = lrelu(as.x + ad.x);
    float e1 = lrelu(as.y + ad.y);
    float e2 = lrelu(as.z + ad.z);
    float e3 = lrelu(as.w + ad.w);
    atomicMax(&g_emax1[dst * 4 + 0], fenc(e0));
    atomicMax(&g_emax1[dst * 4 + 1], fenc(e1));
    atomicMax(&g_emax1[dst * 4 + 2], fenc(e2));
    atomicMax(&g_emax1[dst * 4 + 3], fenc(e3));
}

// ---------------- layer-1 edge pass B: exp-weighted aggregation -------------
// warp per edge; lane l handles channels 4l..4l+3 (head = l>>3)
__global__ void edgeB1_kernel(const void* __restrict__ ei, int e_cnt, int n) {
    int warp = (blockIdx.x * blockDim.x + threadIdx.x) >> 5;
    int lane = threadIdx.x & 31;
    int tot = e_cnt + n;
    if (warp >= tot) return;
    int is64 = g_is64;
    int src, dst;
    if (warp < e_cnt) edge_fetch(ei, e_cnt, warp, is64, src, dst);
    else              src = dst = warp - e_cnt;
    int hd = lane >> 3;
    float ev = lrelu(g_as1[src * 4 + hd] + g_ad1[dst * 4 + hd]);
    float mx = fdec(g_emax1[dst * 4 + hd]);
    float ex = __expf(ev - mx);
    float4 hv = ((const float4*)g_h1)[src * 32 + lane];
    float* p = g_numer1 + dst * 128 + lane * 4;
    asm volatile("red.global.add.v4.f32 [%0], {%1,%2,%3,%4};"
                 :: "l"(p), "f"(hv.x * ex), "f"(hv.y * ex),
                    "f"(hv.z * ex), "f"(hv.w * ex)
                 : "memory");
    if ((lane & 7) == 0) atomicAdd(&g_denom1[dst * 4 + hd], ex);
}

// ---------------- node pass: out1 = relu(numer/denom + b1); h2 = out1 @ W2 --
__global__ void node1_kernel(const float* __restrict__ b1,
                             const float* __restrict__ W2, int n) {
    int warp = (blockIdx.x * blockDim.x + threadIdx.x) >> 5;
    int lane = threadIdx.x & 31;
    if (warp >= n) return;
    int hd = lane >> 3;
    float4 num = ((const float4*)g_numer1)[warp * 32 + lane];
    float inv = 1.f / (g_denom1[warp * 4 + hd] + 1e-16f);
    float4 bb = ((const float4*)b1)[lane];
    float x0 = fmaxf(num.x * inv + bb.x, 0.f);
    float x1 = fmaxf(num.y * inv + bb.y, 0.f);
    float x2 = fmaxf(num.z * inv + bb.z, 0.f);
    float x3 = fmaxf(num.w * inv + bb.w, 0.f);
    float4 w = ((const float4*)W2)[lane];
    float s = x0 * w.x + x1 * w.y + x2 * w.z + x3 * w.w;
#pragma unroll
    for (int o = 16; o > 0; o >>= 1) s += __shfl_xor_sync(0xffffffffu, s, o);
    if (lane == 0) g_h2[warp] = s;
}

// ---------------- layer-2 edge passes (scalar head) --------------------------
__global__ void edgeA2_kernel(const void* __restrict__ ei,
                              const float* __restrict__ att_s2,
                              const float* __restrict__ att_d2,
                              int e_cnt, int n) {
    int i = blockIdx.x * blockDim.x + threadIdx.x;
    int tot = e_cnt + n;
    if (i >= tot) return;
    int is64 = g_is64;
    int src, dst;
    if (i < e_cnt) edge_fetch(ei, e_cnt, i, is64, src, dst);
    else           src = dst = i - e_cnt;
    float e = lrelu(g_h2[src] * att_s2[0] + g_h2[dst] * att_d2[0]);
    atomicMax(&g_emax2[dst], fenc(e));
}

__global__ void edgeB2_kernel(const void* __restrict__ ei,
                              const float* __restrict__ att_s2,
                              const float* __restrict__ att_d2,
                              int e_cnt, int n) {
    int i = blockIdx.x * blockDim.x + threadIdx.x;
    int tot = e_cnt + n;
    if (i >= tot) return;
    int is64 = g_is64;
    int src, dst;
    if (i < e_cnt) edge_fetch(ei, e_cnt, i, is64, src, dst);
    else           src = dst = i - e_cnt;
    float hs = g_h2[src];
    float e = lrelu(hs * att_s2[0] + g_h2[dst] * att_d2[0]);
    float ex = __expf(e - fdec(g_emax2[dst]));
    atomicAdd(&g_denom2[dst], ex);
    atomicAdd(&g_numer2[dst], hs * ex);
}

__global__ void out_kernel(const float* __restrict__ b2, float* __restrict__ out,
                           int n) {
    int i = blockIdx.x * blockDim.x + threadIdx.x;
    if (i >= n) return;
    out[i] = g_numer2[i] / (g_denom2[i] + 1e-16f) + b2[0];
}

// ---------------- launch ------------------------------------------------------
extern "C" void kernel_launch(void* const* d_in, const int* in_sizes, int n_in,
                              void* d_out, int out_size) {
    const float* x        = (const float*)d_in[0];
    const void*  ei       = d_in[1];
    const float* W1       = (const float*)d_in[2];
    const float* att_src1 = (const float*)d_in[3];
    const float* att_dst1 = (const float*)d_in[4];
    const float* b1       = (const float*)d_in[5];
    const float* W2       = (const float*)d_in[6];
    const float* att_src2 = (const float*)d_in[7];
    const float* att_dst2 = (const float*)d_in[8];
    const float* b2       = (const float*)d_in[9];
    float* out = (float*)d_out;

    int n = in_sizes[0] / 128;
    int e = in_sizes[1] / 2;
    int tot = e + n;

    void *p_emax1, *p_denom1, *p_numer1, *p_emax2, *p_denom2, *p_numer2;
    cudaGetSymbolAddress(&p_emax1,  g_emax1);
    cudaGetSymbolAddress(&p_denom1, g_denom1);
    cudaGetSymbolAddress(&p_numer1, g_numer1);
    cudaGetSymbolAddress(&p_emax2,  g_emax2);
    cudaGetSymbolAddress(&p_denom2, g_denom2);
    cudaGetSymbolAddress(&p_numer2, g_numer2);
    cudaMemsetAsync(p_emax1,  0, (size_t)n * 4 * sizeof(unsigned));
    cudaMemsetAsync(p_denom1, 0, (size_t)n * 4 * sizeof(float));
    cudaMemsetAsync(p_numer1, 0, (size_t)n * 128 * sizeof(float));
    cudaMemsetAsync(p_emax2,  0, (size_t)n * sizeof(unsigned));
    cudaMemsetAsync(p_denom2, 0, (size_t)n * sizeof(float));
    cudaMemsetAsync(p_numer2, 0, (size_t)n * sizeof(float));

    int smem = (128 * 128 + 64 * 128) * sizeof(float);  // 98304
    cudaFuncSetAttribute(gemm1_kernel,
                         cudaFuncAttributeMaxDynamicSharedMemorySize, smem);

    detect_kernel<<<1, 256>>>((const unsigned*)ei, e);
    gemm1_kernel<<<(n + 63) / 64, 256, smem>>>(x, W1, n);
    att1_kernel<<<(n + 7) / 8, 256>>>(att_src1, att_dst1, n);
    edgeA1_kernel<<<(tot + 255) / 256, 256>>>(ei, e, n);
    edgeB1_kernel<<<(tot + 7) / 8, 256>>>(ei, e, n);
    node1_kernel<<<(n + 7) / 8, 256>>>(b1, W2, n);
    edgeA2_kernel<<<(tot + 255) / 256, 256>>>(ei, att_src2, att_dst2, e, n);
    edgeB2_kernel<<<(tot + 255) / 256, 256>>>(ei, att_src2, att_dst2, e, n);
    out_kernel<<<(n + 255) / 256, 256>>>(b2, out, n);
}

// round 3
// speedup vs baseline: 2.0000x; 2.0000x over previous
#include <cuda_runtime.h>

#define MAXN 100000
#define MAXE 1600000
#define SCAN_BLK 1024

// ---------------- scratch (device globals; no allocations allowed) ----------
__device__ __align__(16) float    g_h1[MAXN * 128];
__device__ __align__(16) float    g_as1[MAXN * 4];
__device__ __align__(16) float    g_ad1[MAXN * 4];
__device__ float                  g_h2[MAXN];
__device__ int                    g_is64;
// CSR scratch
__device__ int g_deg[MAXN];
__device__ int g_rowptr[MAXN + 1];
__device__ int g_cursor[MAXN];
__device__ int g_blocksum[256];
__device__ int g_esrc[MAXE + MAXN];

__device__ __forceinline__ float lrelu(float v) { return v > 0.f ? v : 0.2f * v; }

// Edge fetch that works for both int32 and int64 edge_index layouts.
__device__ __forceinline__ void edge_fetch(const void* ei, int e_cnt, int i,
                                           int is64, int& src, int& dst) {
    if (is64) {
        const long long* p = (const long long*)ei;
        src = (int)p[i];
        dst = (int)p[e_cnt + i];
    } else {
        const int* p = (const int*)ei;
        src = p[i];
        dst = p[e_cnt + i];
    }
}

// ---------------- dtype detection: int64 iff all sampled high-words are 0 ---
__global__ void detect_kernel(const unsigned* __restrict__ ei_u32, int e_cnt) {
    __shared__ int bad;
    if (threadIdx.x == 0) bad = 0;
    __syncthreads();
    int samples = e_cnt < 4096 ? e_cnt : 4096;
    for (int i = threadIdx.x; i < samples; i += blockDim.x) {
        if (ei_u32[2 * i + 1] != 0u) bad = 1;
    }
    __syncthreads();
    if (threadIdx.x == 0) g_is64 = bad ? 0 : 1;
}

// ---------------- CSR build --------------------------------------------------
__global__ void hist_kernel(const void* __restrict__ ei, int e_cnt, int n) {
    int i = blockIdx.x * blockDim.x + threadIdx.x;
    int tot = e_cnt + n;
    if (i >= tot) return;
    int is64 = g_is64;
    int src, dst;
    if (i < e_cnt) edge_fetch(ei, e_cnt, i, is64, src, dst);
    else           dst = i - e_cnt;
    atomicAdd(&g_deg[dst], 1);
}

// per-block exclusive scan (within block); blocksum[b] = block total
__global__ void scan_block_kernel(int n) {
    __shared__ int s[SCAN_BLK];
    int t = threadIdx.x;
    int i = blockIdx.x * SCAN_BLK + t;
    int val = (i < n) ? g_deg[i] : 0;
    s[t] = val;
    __syncthreads();
#pragma unroll
    for (int off = 1; off < SCAN_BLK; off <<= 1) {
        int v2 = (t >= off) ? s[t - off] : 0;
        __syncthreads();
        s[t] += v2;
        __syncthreads();
    }
    if (i < n) g_rowptr[i] = s[t] - val;          // exclusive within block
    if (t == SCAN_BLK - 1) g_blocksum[blockIdx.x] = s[t];
}

__global__ void scan_top_kernel(int nb) {
    if (threadIdx.x == 0) {
        int acc = 0;
        for (int b = 0; b < nb; b++) {
            int x = g_blocksum[b];
            g_blocksum[b] = acc;
            acc += x;
        }
    }
}

__global__ void scan_add_kernel(int n, int tot) {
    int i = blockIdx.x * SCAN_BLK + threadIdx.x;
    if (i < n) {
        int r = g_rowptr[i] + g_blocksum[blockIdx.x];
        g_rowptr[i] = r;
        g_cursor[i] = r;
    }
    if (i == 0) g_rowptr[n] = tot;
}

__global__ void scatter_kernel(const void* __restrict__ ei, int e_cnt, int n) {
    int i = blockIdx.x * blockDim.x + threadIdx.x;
    int tot = e_cnt + n;
    if (i >= tot) return;
    int is64 = g_is64;
    int src, dst;
    if (i < e_cnt) edge_fetch(ei, e_cnt, i, is64, src, dst);
    else           src = dst = i - e_cnt;
    int pos = atomicAdd(&g_cursor[dst], 1);
    g_esrc[pos] = src;
}

// ---------------- GEMM1: h1 = x @ W1  ([n,128] x [128,128]) -----------------
__global__ void gemm1_kernel(const float* __restrict__ x,
                             const float* __restrict__ W, int n) {
    extern __shared__ float sm[];
    float4* Ws4 = (float4*)sm;                 // 128*128 floats
    float4* Xs4 = (float4*)(sm + 128 * 128);   // 64*128 floats
    int t = threadIdx.x;

    const float4* Wg4 = (const float4*)W;
#pragma unroll
    for (int i = 0; i < 16; i++) Ws4[t + i * 256] = Wg4[t + i * 256];

    int row0 = blockIdx.x * 64;
    const float4* Xg4 = (const float4*)x;
#pragma unroll
    for (int i = 0; i < 8; i++) {
        int idx = t + i * 256;
        int r = idx >> 5;
        float4 v = make_float4(0.f, 0.f, 0.f, 0.f);
        if (row0 + r < n) v = Xg4[(row0 + r) * 32 + (idx & 31)];
        Xs4[idx] = v;
    }
    __syncthreads();

    int cg = t & 31;
    int rg = t >> 5;
    float4 acc[8];
#pragma unroll
    for (int j = 0; j < 8; j++) acc[j] = make_float4(0.f, 0.f, 0.f, 0.f);

    for (int k = 0; k < 128; k += 4) {
        float4 b0 = Ws4[(k + 0) * 32 + cg];
        float4 b1 = Ws4[(k + 1) * 32 + cg];
        float4 b2 = Ws4[(k + 2) * 32 + cg];
        float4 b3 = Ws4[(k + 3) * 32 + cg];
#pragma unroll
        for (int j = 0; j < 8; j++) {
            float4 a = Xs4[(rg * 8 + j) * 32 + (k >> 2)];
            acc[j].x += a.x * b0.x + a.y * b1.x + a.z * b2.x + a.w * b3.x;
            acc[j].y += a.x * b0.y + a.y * b1.y + a.z * b2.y + a.w * b3.y;
            acc[j].z += a.x * b0.z + a.y * b1.z + a.z * b2.z + a.w * b3.z;
            acc[j].w += a.x * b0.w + a.y * b1.w + a.z * b2.w + a.w * b3.w;
        }
    }

    float4* Hg4 = (float4*)g_h1;
#pragma unroll
    for (int j = 0; j < 8; j++) {
        int r = row0 + rg * 8 + j;
        if (r < n) Hg4[r * 32 + cg] = acc[j];
    }
}

// ---------------- attention coefficients: a_s, a_d (warp per node) ----------
__global__ void att1_kernel(const float* __restrict__ att_src,
                            const float* __restrict__ att_dst, int n) {
    int warp = (blockIdx.x * blockDim.x + threadIdx.x) >> 5;
    int lane = threadIdx.x & 31;
    if (warp >= n) return;
    float s0, s1, s2, s3, d0, d1, d2, d3;
    {
        float h0 = g_h1[warp * 128 + 0 * 32 + lane];
        float h1 = g_h1[warp * 128 + 1 * 32 + lane];
        float h2 = g_h1[warp * 128 + 2 * 32 + lane];
        float h3 = g_h1[warp * 128 + 3 * 32 + lane];
        s0 = h0 * att_src[0 * 32 + lane]; d0 = h0 * att_dst[0 * 32 + lane];
        s1 = h1 * att_src[1 * 32 + lane]; d1 = h1 * att_dst[1 * 32 + lane];
        s2 = h2 * att_src[2 * 32 + lane]; d2 = h2 * att_dst[2 * 32 + lane];
        s3 = h3 * att_src[3 * 32 + lane]; d3 = h3 * att_dst[3 * 32 + lane];
    }
#pragma unroll
    for (int o = 16; o > 0; o >>= 1) {
        s0 += __shfl_xor_sync(0xffffffffu, s0, o);
        s1 += __shfl_xor_sync(0xffffffffu, s1, o);
        s2 += __shfl_xor_sync(0xffffffffu, s2, o);
        s3 += __shfl_xor_sync(0xffffffffu, s3, o);
        d0 += __shfl_xor_sync(0xffffffffu, d0, o);
        d1 += __shfl_xor_sync(0xffffffffu, d1, o);
        d2 += __shfl_xor_sync(0xffffffffu, d2, o);
        d3 += __shfl_xor_sync(0xffffffffu, d3, o);
    }
    if (lane == 0) {
        ((float4*)g_as1)[warp] = make_float4(s0, s1, s2, s3);
        ((float4*)g_ad1)[warp] = make_float4(d0, d1, d2, d3);
    }
}

// ---------------- layer-1 aggregation (CSR, warp per dst node) --------------
// Lane l owns channels 4l..4l+3 (head hd = l>>3). Accumulates numerator and
// denominator in registers; epilogue fuses bias+relu and the [128]x[128,1]
// GEMM2 projection -> g_h2. No atomics, no numer/denom arrays.
__global__ void agg1_kernel(const float* __restrict__ b1,
                            const float* __restrict__ W2, int n) {
    int v = (blockIdx.x * blockDim.x + threadIdx.x) >> 5;
    int lane = threadIdx.x & 31;
    if (v >= n) return;
    int hd = lane >> 3;
    int beg = g_rowptr[v];
    int end = g_rowptr[v + 1];
    float adv = g_ad1[v * 4 + hd];

    float4 acc = make_float4(0.f, 0.f, 0.f, 0.f);
    float den = 0.f;
    const float4* H4 = (const float4*)g_h1;

    int e = beg;
#pragma unroll 2
    for (; e + 1 < end; e += 2) {
        int s0 = g_esrc[e];
        int s1 = g_esrc[e + 1];
        float a0 = g_as1[s0 * 4 + hd];
        float a1 = g_as1[s1 * 4 + hd];
        float4 hv0 = H4[s0 * 32 + lane];
        float4 hv1 = H4[s1 * 32 + lane];
        float ex0 = __expf(lrelu(a0 + adv));
        float ex1 = __expf(lrelu(a1 + adv));
        den += ex0 + ex1;
        acc.x += hv0.x * ex0 + hv1.x * ex1;
        acc.y += hv0.y * ex0 + hv1.y * ex1;
        acc.z += hv0.z * ex0 + hv1.z * ex1;
        acc.w += hv0.w * ex0 + hv1.w * ex1;
    }
    if (e < end) {
        int s0 = g_esrc[e];
        float ex0 = __expf(lrelu(g_as1[s0 * 4 + hd] + adv));
        float4 hv0 = H4[s0 * 32 + lane];
        den += ex0;
        acc.x += hv0.x * ex0;
        acc.y += hv0.y * ex0;
        acc.z += hv0.z * ex0;
        acc.w += hv0.w * ex0;
    }

    float inv = 1.f / (den + 1e-16f);
    float4 bb = ((const float4*)b1)[lane];
    float4 w  = ((const float4*)W2)[lane];
    float x0 = fmaxf(acc.x * inv + bb.x, 0.f);
    float x1 = fmaxf(acc.y * inv + bb.y, 0.f);
    float x2 = fmaxf(acc.z * inv + bb.z, 0.f);
    float x3 = fmaxf(acc.w * inv + bb.w, 0.f);
    float s = x0 * w.x + x1 * w.y + x2 * w.z + x3 * w.w;
#pragma unroll
    for (int o = 16; o > 0; o >>= 1) s += __shfl_xor_sync(0xffffffffu, s, o);
    if (lane == 0) g_h2[v] = s;
}

// ---------------- layer-2 aggregation (CSR, thread per dst node) ------------
__global__ void agg2_kernel(const float* __restrict__ att_s2,
                            const float* __restrict__ att_d2,
                            const float* __restrict__ b2,
                            float* __restrict__ out, int n) {
    int v = blockIdx.x * blockDim.x + threadIdx.x;
    if (v >= n) return;
    float as2 = att_s2[0];
    float adv = g_h2[v] * att_d2[0];
    int beg = g_rowptr[v];
    int end = g_rowptr[v + 1];
    float den = 0.f, num = 0.f;
    int e = beg;
#pragma unroll 2
    for (; e + 1 < end; e += 2) {
        int s0 = g_esrc[e];
        int s1 = g_esrc[e + 1];
        float h0 = g_h2[s0];
        float h1 = g_h2[s1];
        float ex0 = __expf(lrelu(h0 * as2 + adv));
        float ex1 = __expf(lrelu(h1 * as2 + adv));
        den += ex0 + ex1;
        num += h0 * ex0 + h1 * ex1;
    }
    if (e < end) {
        float h0 = g_h2[g_esrc[e]];
        float ex0 = __expf(lrelu(h0 * as2 + adv));
        den += ex0;
        num += h0 * ex0;
    }
    out[v] = num / (den + 1e-16f) + b2[0];
}

// ---------------- launch ------------------------------------------------------
extern "C" void kernel_launch(void* const* d_in, const int* in_sizes, int n_in,
                              void* d_out, int out_size) {
    const float* x        = (const float*)d_in[0];
    const void*  ei       = d_in[1];
    const float* W1       = (const float*)d_in[2];
    const float* att_src1 = (const float*)d_in[3];
    const float* att_dst1 = (const float*)d_in[4];
    const float* b1       = (const float*)d_in[5];
    const float* W2       = (const float*)d_in[6];
    const float* att_src2 = (const float*)d_in[7];
    const float* att_dst2 = (const float*)d_in[8];
    const float* b2       = (const float*)d_in[9];
    float* out = (float*)d_out;

    int n = in_sizes[0] / 128;
    int e = in_sizes[1] / 2;
    int tot = e + n;
    int nb = (n + SCAN_BLK - 1) / SCAN_BLK;

    void* p_deg;
    cudaGetSymbolAddress(&p_deg, g_deg);
    cudaMemsetAsync(p_deg, 0, (size_t)n * sizeof(int));

    int smem = (128 * 128 + 64 * 128) * sizeof(float);  // 98304
    cudaFuncSetAttribute(gemm1_kernel,
                         cudaFuncAttributeMaxDynamicSharedMemorySize, smem);

    detect_kernel<<<1, 256>>>((const unsigned*)ei, e);
    // CSR build
    hist_kernel<<<(tot + 255) / 256, 256>>>(ei, e, n);
    scan_block_kernel<<<nb, SCAN_BLK>>>(n);
    scan_top_kernel<<<1, 32>>>(nb);
    scan_add_kernel<<<nb, SCAN_BLK>>>(n, tot);
    scatter_kernel<<<(tot + 255) / 256, 256>>>(ei, e, n);
    // layer 1
    gemm1_kernel<<<(n + 63) / 64, 256, smem>>>(x, W1, n);
    att1_kernel<<<(n + 7) / 8, 256>>>(att_src1, att_dst1, n);
    agg1_kernel<<<(n + 7) / 8, 256>>>(b1, W2, n);
    // layer 2
    agg2_kernel<<<(n + 255) / 256, 256>>>(att_src2, att_dst2, b2, out, n);
}

// round 4
// speedup vs baseline: 2.2129x; 1.1064x over previous
#include <cuda_runtime.h>
#include <cuda_fp16.h>

#define MAXN 100000
#define MAXE 1600000
#define SCAN_BLK 1024

// ---------------- scratch (device globals; no allocations allowed) ----------
__device__ __align__(16) __half2  g_h1h[MAXN * 64];   // h1 in fp16, 128 ch/row
__device__ __align__(16) float    g_as1[MAXN * 4];
__device__ __align__(16) float    g_ad1[MAXN * 4];
__device__ float                  g_h2[MAXN];
__device__ int                    g_is64;
// CSR scratch
__device__ int g_deg[MAXN];
__device__ int g_rowptr[MAXN + 1];
__device__ int g_cursor[MAXN];
__device__ int g_blocksum[256];
__device__ int g_esrc[MAXE + MAXN];

__device__ __forceinline__ float lrelu(float v) { return v > 0.f ? v : 0.2f * v; }

// Edge fetch that works for both int32 and int64 edge_index layouts.
__device__ __forceinline__ void edge_fetch(const void* ei, int e_cnt, int i,
                                           int is64, int& src, int& dst) {
    if (is64) {
        const long long* p = (const long long*)ei;
        src = (int)p[i];
        dst = (int)p[e_cnt + i];
    } else {
        const int* p = (const int*)ei;
        src = p[i];
        dst = p[e_cnt + i];
    }
}

// ---------------- dtype detection: int64 iff all sampled high-words are 0 ---
__global__ void detect_kernel(const unsigned* __restrict__ ei_u32, int e_cnt) {
    __shared__ int bad;
    if (threadIdx.x == 0) bad = 0;
    __syncthreads();
    int samples = e_cnt < 4096 ? e_cnt : 4096;
    for (int i = threadIdx.x; i < samples; i += blockDim.x) {
        if (ei_u32[2 * i + 1] != 0u) bad = 1;
    }
    __syncthreads();
    if (threadIdx.x == 0) g_is64 = bad ? 0 : 1;
}

// ---------------- CSR build --------------------------------------------------
__global__ void hist_kernel(const void* __restrict__ ei, int e_cnt, int n) {
    int i = blockIdx.x * blockDim.x + threadIdx.x;
    int tot = e_cnt + n;
    if (i >= tot) return;
    int is64 = g_is64;
    int src, dst;
    if (i < e_cnt) edge_fetch(ei, e_cnt, i, is64, src, dst);
    else           dst = i - e_cnt;
    atomicAdd(&g_deg[dst], 1);
}

// per-block inclusive scan -> exclusive; blocksum[b] = block total
__global__ void scan_block_kernel(int n) {
    __shared__ int s[SCAN_BLK];
    int t = threadIdx.x;
    int i = blockIdx.x * SCAN_BLK + t;
    int val = (i < n) ? g_deg[i] : 0;
    s[t] = val;
    __syncthreads();
#pragma unroll
    for (int off = 1; off < SCAN_BLK; off <<= 1) {
        int v2 = (t >= off) ? s[t - off] : 0;
        __syncthreads();
        s[t] += v2;
        __syncthreads();
    }
    if (i < n) g_rowptr[i] = s[t] - val;          // exclusive within block
    if (t == SCAN_BLK - 1) g_blocksum[blockIdx.x] = s[t];
}

// parallel exclusive scan of block sums (nb <= 128)
__global__ void scan_top_kernel(int nb) {
    __shared__ int s[128];
    int t = threadIdx.x;
    int v = (t < nb) ? g_blocksum[t] : 0;
    s[t] = v;
    __syncthreads();
#pragma unroll
    for (int off = 1; off < 128; off <<= 1) {
        int x = (t >= off) ? s[t - off] : 0;
        __syncthreads();
        s[t] += x;
        __syncthreads();
    }
    if (t < nb) g_blocksum[t] = s[t] - v;
}

__global__ void scan_add_kernel(int n, int tot) {
    int i = blockIdx.x * SCAN_BLK + threadIdx.x;
    if (i < n) {
        int r = g_rowptr[i] + g_blocksum[blockIdx.x];
        g_rowptr[i] = r;
        g_cursor[i] = r;
    }
    if (i == 0) g_rowptr[n] = tot;
}

__global__ void scatter_kernel(const void* __restrict__ ei, int e_cnt, int n) {
    int i = blockIdx.x * blockDim.x + threadIdx.x;
    int tot = e_cnt + n;
    if (i >= tot) return;
    int is64 = g_is64;
    int src, dst;
    if (i < e_cnt) edge_fetch(ei, e_cnt, i, is64, src, dst);
    else           src = dst = i - e_cnt;
    int pos = atomicAdd(&g_cursor[dst], 1);
    g_esrc[pos] = src;
}

// ---------------- GEMM1 + fused attention epilogue --------------------------
// h1 = x @ W1  ([n,128] x [128,128]); epilogue stores h1 as fp16 and computes
// a_s / a_d per head in fp32 via 8-lane segmented warp reductions.
__global__ void gemm1_kernel(const float* __restrict__ x,
                             const float* __restrict__ W,
                             const float* __restrict__ att_s,
                             const float* __restrict__ att_d, int n) {
    extern __shared__ float sm[];
    float4* Ws4 = (float4*)sm;                 // 128*128 floats
    float4* Xs4 = (float4*)(sm + 128 * 128);   // 64*128 floats
    int t = threadIdx.x;

    const float4* Wg4 = (const float4*)W;
#pragma unroll
    for (int i = 0; i < 16; i++) Ws4[t + i * 256] = Wg4[t + i * 256];

    int row0 = blockIdx.x * 64;
    const float4* Xg4 = (const float4*)x;
#pragma unroll
    for (int i = 0; i < 8; i++) {
        int idx = t + i * 256;
        int r = idx >> 5;
        float4 v = make_float4(0.f, 0.f, 0.f, 0.f);
        if (row0 + r < n) v = Xg4[(row0 + r) * 32 + (idx & 31)];
        Xs4[idx] = v;
    }
    __syncthreads();

    int cg = t & 31;   // lane; owns cols 4cg..4cg+3
    int rg = t >> 5;   // warp; owns rows rg*8..rg*8+7
    float4 acc[8];
#pragma unroll
    for (int j = 0; j < 8; j++) acc[j] = make_float4(0.f, 0.f, 0.f, 0.f);

    for (int k = 0; k < 128; k += 4) {
        float4 b0 = Ws4[(k + 0) * 32 + cg];
        float4 b1 = Ws4[(k + 1) * 32 + cg];
        float4 b2 = Ws4[(k + 2) * 32 + cg];
        float4 b3 = Ws4[(k + 3) * 32 + cg];
#pragma unroll
        for (int j = 0; j < 8; j++) {
            float4 a = Xs4[(rg * 8 + j) * 32 + (k >> 2)];
            acc[j].x += a.x * b0.x + a.y * b1.x + a.z * b2.x + a.w * b3.x;
            acc[j].y += a.x * b0.y + a.y * b1.y + a.z * b2.y + a.w * b3.y;
            acc[j].z += a.x * b0.z + a.y * b1.z + a.z * b2.z + a.w * b3.z;
            acc[j].w += a.x * b0.w + a.y * b1.w + a.z * b2.w + a.w * b3.w;
        }
    }

    float4 avs = ((const float4*)att_s)[cg];
    float4 avd = ((const float4*)att_d)[cg];
    uint2* H2 = (uint2*)g_h1h;
    int hd = cg >> 3;

#pragma unroll
    for (int j = 0; j < 8; j++) {
        int r = row0 + rg * 8 + j;        // warp-uniform
        if (r < n) {
            __half2 lo = __floats2half2_rn(acc[j].x, acc[j].y);
            __half2 hi = __floats2half2_rn(acc[j].z, acc[j].w);
            uint2 pk;
            pk.x = *(unsigned*)&lo;
            pk.y = *(unsigned*)&hi;
            H2[r * 32 + cg] = pk;
            float s = acc[j].x * avs.x + acc[j].y * avs.y +
                      acc[j].z * avs.z + acc[j].w * avs.w;
            float d = acc[j].x * avd.x + acc[j].y * avd.y +
                      acc[j].z * avd.z + acc[j].w * avd.w;
#pragma unroll
            for (int o = 1; o < 8; o <<= 1) {
                s += __shfl_xor_sync(0xffffffffu, s, o);
                d += __shfl_xor_sync(0xffffffffu, d, o);
            }
            if ((cg & 7) == 0) {
                g_as1[r * 4 + hd] = s;
                g_ad1[r * 4 + hd] = d;
            }
        }
    }
}

// ---------------- layer-1 aggregation (CSR, warp per dst node) --------------
// Lane l owns channels 4l..4l+3 (head hd = l>>3). fp16 gather, fp32 math.
// Epilogue fuses bias+relu and the [128]x[128,1] projection -> g_h2.
__global__ void agg1_kernel(const float* __restrict__ b1,
                            const float* __restrict__ W2, int n) {
    int v = (blockIdx.x * blockDim.x + threadIdx.x) >> 5;
    int lane = threadIdx.x & 31;
    if (v >= n) return;
    int hd = lane >> 3;
    int beg = g_rowptr[v];
    int end = g_rowptr[v + 1];
    float adv = g_ad1[v * 4 + hd];

    float4 acc = make_float4(0.f, 0.f, 0.f, 0.f);
    float den = 0.f;
    const uint2* H2 = (const uint2*)g_h1h;

    int e = beg;
#pragma unroll 2
    for (; e + 1 < end; e += 2) {
        int s0 = g_esrc[e];
        int s1 = g_esrc[e + 1];
        float a0 = g_as1[s0 * 4 + hd];
        float a1 = g_as1[s1 * 4 + hd];
        uint2 p0 = H2[s0 * 32 + lane];
        uint2 p1 = H2[s1 * 32 + lane];
        float ex0 = __expf(lrelu(a0 + adv));
        float ex1 = __expf(lrelu(a1 + adv));
        den += ex0 + ex1;
        float2 l0 = __half22float2(*(__half2*)&p0.x);
        float2 h0 = __half22float2(*(__half2*)&p0.y);
        float2 l1 = __half22float2(*(__half2*)&p1.x);
        float2 h1 = __half22float2(*(__half2*)&p1.y);
        acc.x += l0.x * ex0 + l1.x * ex1;
        acc.y += l0.y * ex0 + l1.y * ex1;
        acc.z += h0.x * ex0 + h1.x * ex1;
        acc.w += h0.y * ex0 + h1.y * ex1;
    }
    if (e < end) {
        int s0 = g_esrc[e];
        float ex0 = __expf(lrelu(g_as1[s0 * 4 + hd] + adv));
        uint2 p0 = H2[s0 * 32 + lane];
        float2 l0 = __half22float2(*(__half2*)&p0.x);
        float2 h0 = __half22float2(*(__half2*)&p0.y);
        den += ex0;
        acc.x += l0.x * ex0;
        acc.y += l0.y * ex0;
        acc.z += h0.x * ex0;
        acc.w += h0.y * ex0;
    }

    float inv = 1.f / (den + 1e-16f);
    float4 bb = ((const float4*)b1)[lane];
    float4 w  = ((const float4*)W2)[lane];
    float x0 = fmaxf(acc.x * inv + bb.x, 0.f);
    float x1 = fmaxf(acc.y * inv + bb.y, 0.f);
    float x2 = fmaxf(acc.z * inv + bb.z, 0.f);
    float x3 = fmaxf(acc.w * inv + bb.w, 0.f);
    float s = x0 * w.x + x1 * w.y + x2 * w.z + x3 * w.w;
#pragma unroll
    for (int o = 16; o > 0; o >>= 1) s += __shfl_xor_sync(0xffffffffu, s, o);
    if (lane == 0) g_h2[v] = s;
}

// ---------------- layer-2 aggregation (CSR, thread per dst node) ------------
__global__ void agg2_kernel(const float* __restrict__ att_s2,
                            const float* __restrict__ att_d2,
                            const float* __restrict__ b2,
                            float* __restrict__ out, int n) {
    int v = blockIdx.x * blockDim.x + threadIdx.x;
    if (v >= n) return;
    float as2 = att_s2[0];
    float adv = g_h2[v] * att_d2[0];
    int beg = g_rowptr[v];
    int end = g_rowptr[v + 1];
    float den = 0.f, num = 0.f;
    int e = beg;
#pragma unroll 2
    for (; e + 1 < end; e += 2) {
        int s0 = g_esrc[e];
        int s1 = g_esrc[e + 1];
        float h0 = g_h2[s0];
        float h1 = g_h2[s1];
        float ex0 = __expf(lrelu(h0 * as2 + adv));
        float ex1 = __expf(lrelu(h1 * as2 + adv));
        den += ex0 + ex1;
        num += h0 * ex0 + h1 * ex1;
    }
    if (e < end) {
        float h0 = g_h2[g_esrc[e]];
        float ex0 = __expf(lrelu(h0 * as2 + adv));
        den += ex0;
        num += h0 * ex0;
    }
    out[v] = num / (den + 1e-16f) + b2[0];
}

// ---------------- launch ------------------------------------------------------
extern "C" void kernel_launch(void* const* d_in, const int* in_sizes, int n_in,
                              void* d_out, int out_size) {
    const float* x        = (const float*)d_in[0];
    const void*  ei       = d_in[1];
    const float* W1       = (const float*)d_in[2];
    const float* att_src1 = (const float*)d_in[3];
    const float* att_dst1 = (const float*)d_in[4];
    const float* b1       = (const float*)d_in[5];
    const float* W2       = (const float*)d_in[6];
    const float* att_src2 = (const float*)d_in[7];
    const float* att_dst2 = (const float*)d_in[8];
    const float* b2       = (const float*)d_in[9];
    float* out = (float*)d_out;

    int n = in_sizes[0] / 128;
    int e = in_sizes[1] / 2;
    int tot = e + n;
    int nb = (n + SCAN_BLK - 1) / SCAN_BLK;

    void* p_deg;
    cudaGetSymbolAddress(&p_deg, g_deg);
    cudaMemsetAsync(p_deg, 0, (size_t)n * sizeof(int));

    int smem = (128 * 128 + 64 * 128) * sizeof(float);  // 98304
    cudaFuncSetAttribute(gemm1_kernel,
                         cudaFuncAttributeMaxDynamicSharedMemorySize, smem);

    detect_kernel<<<1, 256>>>((const unsigned*)ei, e);
    // CSR build
    hist_kernel<<<(tot + 255) / 256, 256>>>(ei, e, n);
    scan_block_kernel<<<nb, SCAN_BLK>>>(n);
    scan_top_kernel<<<1, 128>>>(nb);
    scan_add_kernel<<<nb, SCAN_BLK>>>(n, tot);
    scatter_kernel<<<(tot + 255) / 256, 256>>>(ei, e, n);
    // layer 1 (GEMM + fused attention coefs)
    gemm1_kernel<<<(n + 63) / 64, 256, smem>>>(x, W1, att_src1, att_dst1, n);
    agg1_kernel<<<(n + 7) / 8, 256>>>(b1, W2, n);
    // layer 2
    agg2_kernel<<<(n + 255) / 256, 256>>>(att_src2, att_dst2, b2, out, n);
}

// round 6
// speedup vs baseline: 2.6135x; 1.1811x over previous
#include <cuda_runtime.h>
#include <cuda_fp16.h>

#define MAXN 100000
#define MAXE 1600000
#define SCAN_BLK 1024

// ---------------- scratch (device globals; no allocations allowed) ----------
__device__ __align__(16) __half2  g_h1h[MAXN * 64];   // h1 fp16, 128 ch/row
__device__ __align__(16) float    g_as1[MAXN * 4];
__device__ __align__(16) float    g_ad1[MAXN * 4];
__device__ float                  g_h2[MAXN];
__device__ int                    g_is64;
__device__ int g_deg[MAXN];
__device__ int g_rowptr[MAXN + 1];
__device__ int g_cursor[MAXN];
__device__ int g_esrc[MAXE + MAXN];
__device__ unsigned long long g_scanpack[128];        // (flag<<32)|value
// W1 as fp16 hi/lo, stored [n][k] row-major (k contiguous) for mma B operand
__device__ __align__(16) __half g_W1h_hi[128 * 128];
__device__ __align__(16) __half g_W1h_lo[128 * 128];

__device__ __forceinline__ float lrelu(float v) { return v > 0.f ? v : 0.2f * v; }

__device__ __forceinline__ void edge_fetch(const void* ei, int e_cnt, int i,
                                           int is64, int& src, int& dst) {
    if (is64) {
        const long long* p = (const long long*)ei;
        src = (int)p[i];
        dst = (int)p[e_cnt + i];
    } else {
        const int* p = (const int*)ei;
        src = p[i];
        dst = p[e_cnt + i];
    }
}

__device__ __forceinline__ unsigned smem_u32(const void* p) {
    unsigned a;
    asm("{ .reg .u64 t; cvta.to.shared.u64 t, %1; cvt.u32.u64 %0, t; }"
        : "=r"(a) : "l"(p));
    return a;
}

__device__ __forceinline__ void ldsm_x4(unsigned* r, unsigned addr) {
    asm volatile("ldmatrix.sync.aligned.m8n8.x4.shared.b16 {%0,%1,%2,%3}, [%4];"
                 : "=r"(r[0]), "=r"(r[1]), "=r"(r[2]), "=r"(r[3]) : "r"(addr));
}
__device__ __forceinline__ void ldsm_x2(unsigned* r, unsigned addr) {
    asm volatile("ldmatrix.sync.aligned.m8n8.x2.shared.b16 {%0,%1}, [%2];"
                 : "=r"(r[0]), "=r"(r[1]) : "r"(addr));
}
__device__ __forceinline__ void mma16816(float* d, const unsigned* a,
                                         const unsigned* b) {
    asm volatile(
        "mma.sync.aligned.m16n8k16.row.col.f32.f16.f16.f32 "
        "{%0,%1,%2,%3}, {%4,%5,%6,%7}, {%8,%9}, {%0,%1,%2,%3};"
        : "+f"(d[0]), "+f"(d[1]), "+f"(d[2]), "+f"(d[3])
        : "r"(a[0]), "r"(a[1]), "r"(a[2]), "r"(a[3]), "r"(b[0]), "r"(b[1]));
}

// ---------------- init: zero deg + scan flags, detect dtype, convert W ------
__global__ void detect_init_kernel(const unsigned* __restrict__ ei_u32,
                                   int e_cnt, int n,
                                   const float* __restrict__ W) {
    int gid = blockIdx.x * blockDim.x + threadIdx.x;
    int stride = gridDim.x * blockDim.x;
    for (int i = gid; i < n; i += stride) g_deg[i] = 0;
    if (gid < 128) g_scanpack[gid] = 0ull;
    for (int i = gid; i < 128 * 128; i += stride) {
        int k = i >> 7, nn = i & 127;          // W[k][nn] -> B[nn][k]
        float w = W[i];
        __half hi = __float2half_rn(w);
        __half lo = __float2half_rn(w - __half2float(hi));
        g_W1h_hi[nn * 128 + k] = hi;
        g_W1h_lo[nn * 128 + k] = lo;
    }
    if (blockIdx.x == 0) {
        __shared__ int bad;
        if (threadIdx.x == 0) bad = 0;
        __syncthreads();
        int samples = e_cnt < 4096 ? e_cnt : 4096;
        for (int i = threadIdx.x; i < samples; i += blockDim.x)
            if (ei_u32[2 * i + 1] != 0u) bad = 1;
        __syncthreads();
        if (threadIdx.x == 0) g_is64 = bad ? 0 : 1;
    }
}

// ---------------- CSR: histogram ---------------------------------------------
__global__ void hist_kernel(const void* __restrict__ ei, int e_cnt, int n) {
    int i = blockIdx.x * blockDim.x + threadIdx.x;
    int tot = e_cnt + n;
    if (i >= tot) return;
    int is64 = g_is64;
    int src, dst;
    if (i < e_cnt) edge_fetch(ei, e_cnt, i, is64, src, dst);
    else           dst = i - e_cnt;
    atomicAdd(&g_deg[dst], 1);
}

// ---------------- CSR: single-pass scan (decoupled lookback) -----------------
__global__ void scan_kernel(int n, int tot) {
    __shared__ int s[SCAN_BLK];
    __shared__ int s_prev;
    int t = threadIdx.x, b = blockIdx.x;
    int i = b * SCAN_BLK + t;
    int val = (i < n) ? g_deg[i] : 0;
    s[t] = val;
    __syncthreads();
#pragma unroll
    for (int off = 1; off < SCAN_BLK; off <<= 1) {
        int v2 = (t >= off) ? s[t - off] : 0;
        __syncthreads();
        s[t] += v2;
        __syncthreads();
    }
    int agg = s[SCAN_BLK - 1];
    if (b == 0) {
        if (t == 0) {
            *(volatile unsigned long long*)&g_scanpack[0] =
                (2ull << 32) | (unsigned)agg;
            s_prev = 0;
        }
    } else if (t < 32) {
        if (t == 0)
            *(volatile unsigned long long*)&g_scanpack[b] =
                (1ull << 32) | (unsigned)agg;
        __syncwarp();
        int lane = t;
        int sum = 0;
        int base = b - 1;
        for (;;) {
            int j = base - lane;
            unsigned long long w;
            unsigned f;
            for (;;) {
                w = (j >= 0) ? *(volatile unsigned long long*)&g_scanpack[j]
                             : (2ull << 32);
                f = (unsigned)(w >> 32);
                if (__all_sync(0xffffffffu, f != 0u)) break;
            }
            unsigned m2 = __ballot_sync(0xffffffffu, f == 2u);
            int fl = m2 ? (__ffs(m2) - 1) : 32;
            int take = (lane <= fl) ? (int)(unsigned)w : 0;
#pragma unroll
            for (int o = 16; o > 0; o >>= 1)
                take += __shfl_xor_sync(0xffffffffu, take, o);
            sum += take;
            if (m2) break;
            base -= 32;
        }
        if (t == 0) {
            *(volatile unsigned long long*)&g_scanpack[b] =
                (2ull << 32) | (unsigned)(sum + agg);
            s_prev = sum;
        }
    }
    __syncthreads();
    int pre = s_prev;
    if (i < n) {
        int r = pre + s[t] - val;
        g_rowptr[i] = r;
        g_cursor[i] = r;
    }
    if (i == 0) g_rowptr[n] = tot;
}

// ---------------- CSR: scatter ------------------------------------------------
__global__ void scatter_kernel(const void* __restrict__ ei, int e_cnt, int n) {
    int i = blockIdx.x * blockDim.x + threadIdx.x;
    int tot = e_cnt + n;
    if (i >= tot) return;
    int is64 = g_is64;
    int src, dst;
    if (i < e_cnt) edge_fetch(ei, e_cnt, i, is64, src, dst);
    else           src = dst = i - e_cnt;
    int pos = atomicAdd(&g_cursor[dst], 1);
    g_esrc[pos] = src;
}

// ---------------- GEMM1 via HMMA mma.sync, split-fp16, fused att epilogue ---
// Per CTA: 128 rows x 128 cols x K=128. 8 warps; warp w owns m-strip w*16.
// smem tiles padded to 136 halves/row (272 B) for conflict-free ldmatrix.
#define TS 136
#define TILE_B (128 * TS * 2)          // 34816 bytes
#define OFF_AH 0
#define OFF_AL TILE_B
#define OFF_BH (2 * TILE_B)
#define OFF_BL (3 * TILE_B)
#define GEMM_SMEM (4 * TILE_B)         // 139264

__global__ void __launch_bounds__(256, 1)
gemm1_kernel(const float* __restrict__ x,
             const float* __restrict__ att_s,
             const float* __restrict__ att_d, int n) {
    extern __shared__ char smc[];
    unsigned sbase = smem_u32(smc);
    int t = threadIdx.x, lane = t & 31, w = t >> 5;

    // B tiles: copy [n][k] fp16 images into padded smem rows
    {
        const uint4* bh = (const uint4*)g_W1h_hi;
        const uint4* bl = (const uint4*)g_W1h_lo;
#pragma unroll
        for (int i = 0; i < 8; i++) {
            int idx = t + i * 256;         // 0..2047 uint4s (16 per row)
            int row = idx >> 4, c8 = idx & 15;
            *(uint4*)(smc + OFF_BH + row * 272 + c8 * 16) = bh[idx];
            *(uint4*)(smc + OFF_BL + row * 272 + c8 * 16) = bl[idx];
        }
    }

    // A tile: load x fp32, split hi/lo fp16 into padded smem rows
    {
        int m = t >> 1, half = t & 1;
        int row = blockIdx.x * 128 + m;
        const float4* xr = (const float4*)(x + (size_t)row * 128 + half * 64);
#pragma unroll 4
        for (int j = 0; j < 16; j++) {
            float4 v = make_float4(0.f, 0.f, 0.f, 0.f);
            if (row < n) v = xr[j];
            __half h0 = __float2half_rn(v.x), h1 = __float2half_rn(v.y);
            __half h2 = __float2half_rn(v.z), h3 = __float2half_rn(v.w);
            __half l0 = __float2half_rn(v.x - __half2float(h0));
            __half l1 = __float2half_rn(v.y - __half2float(h1));
            __half l2 = __float2half_rn(v.z - __half2float(h2));
            __half l3 = __float2half_rn(v.w - __half2float(h3));
            int k = half * 64 + 4 * j;
            unsigned off = (unsigned)(m * 272 + k * 2);
            __half2 hp0 = __halves2half2(h0, h1), hp1 = __halves2half2(h2, h3);
            __half2 lp0 = __halves2half2(l0, l1), lp1 = __halves2half2(l2, l3);
            uint2 hp, lp;
            hp.x = *(unsigned*)&hp0; hp.y = *(unsigned*)&hp1;
            lp.x = *(unsigned*)&lp0; lp.y = *(unsigned*)&lp1;
            *(uint2*)(smc + OFF_AH + off) = hp;
            *(uint2*)(smc + OFF_AL + off) = lp;
        }
    }
    __syncthreads();

    int m0 = w * 16;
    float acc[16][4];
#pragma unroll
    for (int nt = 0; nt < 16; nt++)
#pragma unroll
        for (int j = 0; j < 4; j++) acc[nt][j] = 0.f;

    unsigned aBase = sbase + OFF_AH +
        (unsigned)((m0 + (lane & 15)) * 272 + ((lane >> 4) * 8) * 2);
    unsigned bRow  = (unsigned)(lane & 7);
    unsigned bKoff = (unsigned)(((lane >> 3) & 1) * 8);

    for (int kt = 0; kt < 8; kt++) {
        unsigned aA = aBase + kt * 32;
        unsigned ah[4], al[4];
        ldsm_x4(ah, aA);
        ldsm_x4(al, aA + TILE_B);
#pragma unroll
        for (int nt = 0; nt < 16; nt++) {
            unsigned bAddr = sbase + OFF_BH +
                (unsigned)((nt * 8 + bRow) * 272 + (kt * 16 + bKoff) * 2);
            unsigned bh[2], bl[2];
            ldsm_x2(bh, bAddr);
            ldsm_x2(bl, bAddr + TILE_B);
            mma16816(acc[nt], ah, bh);
            mma16816(acc[nt], ah, bl);
            mma16816(acc[nt], al, bh);
        }
    }

    // Epilogue: fragment layout: thread holds rows r0 = m0+lane/4, r1 = r0+8,
    // cols n = nt*8 + 2*(lane%4) + {0,1}. Store fp16 h1 + head reductions.
    {
        int gr = lane >> 2, c = lane & 3;
        int r0 = blockIdx.x * 128 + m0 + gr;
        int r1 = r0 + 8;
        float sv0[4] = {0, 0, 0, 0}, dv0[4] = {0, 0, 0, 0};
        float sv1[4] = {0, 0, 0, 0}, dv1[4] = {0, 0, 0, 0};
#pragma unroll
        for (int nt = 0; nt < 16; nt++) {
            int col = nt * 8 + 2 * c;
            float w0 = att_s[col], w1 = att_s[col + 1];
            float u0 = att_d[col], u1 = att_d[col + 1];
            int hd = nt >> 2;
            sv0[hd] += acc[nt][0] * w0 + acc[nt][1] * w1;
            dv0[hd] += acc[nt][0] * u0 + acc[nt][1] * u1;
            sv1[hd] += acc[nt][2] * w0 + acc[nt][3] * w1;
            dv1[hd] += acc[nt][2] * u0 + acc[nt][3] * u1;
            if (r0 < n)
                g_h1h[(size_t)r0 * 64 + nt * 4 + c] =
                    __floats2half2_rn(acc[nt][0], acc[nt][1]);
            if (r1 < n)
                g_h1h[(size_t)r1 * 64 + nt * 4 + c] =
                    __floats2half2_rn(acc[nt][2], acc[nt][3]);
        }
#pragma unroll
        for (int hd = 0; hd < 4; hd++) {
#pragma unroll
            for (int o = 1; o < 4; o <<= 1) {
                sv0[hd] += __shfl_xor_sync(0xffffffffu, sv0[hd], o);
                dv0[hd] += __shfl_xor_sync(0xffffffffu, dv0[hd], o);
                sv1[hd] += __shfl_xor_sync(0xffffffffu, sv1[hd], o);
                dv1[hd] += __shfl_xor_sync(0xffffffffu, dv1[hd], o);
            }
        }
        if (c == 0) {
#pragma unroll
            for (int hd = 0; hd < 4; hd++) {
                if (r0 < n) {
                    g_as1[r0 * 4 + hd] = sv0[hd];
                    g_ad1[r0 * 4 + hd] = dv0[hd];
                }
                if (r1 < n) {
                    g_as1[r1 * 4 + hd] = sv1[hd];
                    g_ad1[r1 * 4 + hd] = dv1[hd];
                }
            }
        }
    }
}

// ---------------- layer-1 aggregation (CSR, warp per dst node, unroll 4) ----
__global__ void agg1_kernel(const float* __restrict__ b1,
                            const float* __restrict__ W2, int n) {
    int v = (blockIdx.x * blockDim.x + threadIdx.x) >> 5;
    int lane = threadIdx.x & 31;
    if (v >= n) return;
    int hd = lane >> 3;
    int beg = g_rowptr[v];
    int end = g_rowptr[v + 1];
    float adv = g_ad1[v * 4 + hd];

    float4 acc = make_float4(0.f, 0.f, 0.f, 0.f);
    float den = 0.f;
    const uint2* H2 = (const uint2*)g_h1h;

    int e = beg;
    for (; e + 3 < end; e += 4) {
        int s0 = g_esrc[e], s1 = g_esrc[e + 1];
        int s2 = g_esrc[e + 2], s3 = g_esrc[e + 3];
        float a0 = g_as1[s0 * 4 + hd], a1 = g_as1[s1 * 4 + hd];
        float a2 = g_as1[s2 * 4 + hd], a3 = g_as1[s3 * 4 + hd];
        uint2 p0 = H2[s0 * 32 + lane], p1 = H2[s1 * 32 + lane];
        uint2 p2 = H2[s2 * 32 + lane], p3 = H2[s3 * 32 + lane];
        float e0 = __expf(lrelu(a0 + adv)), e1 = __expf(lrelu(a1 + adv));
        float e2 = __expf(lrelu(a2 + adv)), e3 = __expf(lrelu(a3 + adv));
        den += (e0 + e1) + (e2 + e3);
        float2 q;
        q = __half22float2(*(__half2*)&p0.x); acc.x += q.x * e0; acc.y += q.y * e0;
        q = __half22float2(*(__half2*)&p0.y); acc.z += q.x * e0; acc.w += q.y * e0;
        q = __half22float2(*(__half2*)&p1.x); acc.x += q.x * e1; acc.y += q.y * e1;
        q = __half22float2(*(__half2*)&p1.y); acc.z += q.x * e1; acc.w += q.y * e1;
        q = __half22float2(*(__half2*)&p2.x); acc.x += q.x * e2; acc.y += q.y * e2;
        q = __half22float2(*(__half2*)&p2.y); acc.z += q.x * e2; acc.w += q.y * e2;
        q = __half22float2(*(__half2*)&p3.x); acc.x += q.x * e3; acc.y += q.y * e3;
        q = __half22float2(*(__half2*)&p3.y); acc.z += q.x * e3; acc.w += q.y * e3;
    }
    for (; e < end; e++) {
        int s0 = g_esrc[e];
        float e0 = __expf(lrelu(g_as1[s0 * 4 + hd] + adv));
        uint2 p0 = H2[s0 * 32 + lane];
        float2 q;
        den += e0;
        q = __half22float2(*(__half2*)&p0.x); acc.x += q.x * e0; acc.y += q.y * e0;
        q = __half22float2(*(__half2*)&p0.y); acc.z += q.x * e0; acc.w += q.y * e0;
    }

    float inv = 1.f / (den + 1e-16f);
    float4 bb = ((const float4*)b1)[lane];
    float4 w  = ((const float4*)W2)[lane];
    float x0 = fmaxf(acc.x * inv + bb.x, 0.f);
    float x1 = fmaxf(acc.y * inv + bb.y, 0.f);
    float x2 = fmaxf(acc.z * inv + bb.z, 0.f);
    float x3 = fmaxf(acc.w * inv + bb.w, 0.f);
    float s = x0 * w.x + x1 * w.y + x2 * w.z + x3 * w.w;
#pragma unroll
    for (int o = 16; o > 0; o >>= 1) s += __shfl_xor_sync(0xffffffffu, s, o);
    if (lane == 0) g_h2[v] = s;
}

// ---------------- layer-2 aggregation (CSR, thread per dst node) ------------
__global__ void agg2_kernel(const float* __restrict__ att_s2,
                            const float* __restrict__ att_d2,
                            const float* __restrict__ b2,
                            float* __restrict__ out, int n) {
    int v = blockIdx.x * blockDim.x + threadIdx.x;
    if (v >= n) return;
    float as2 = att_s2[0];
    float adv = g_h2[v] * att_d2[0];
    int beg = g_rowptr[v];
    int end = g_rowptr[v + 1];
    float den = 0.f, num = 0.f;
    int e = beg;
#pragma unroll 2
    for (; e + 1 < end; e += 2) {
        int s0 = g_esrc[e];
        int s1 = g_esrc[e + 1];
        float h0 = g_h2[s0];
        float h1 = g_h2[s1];
        float ex0 = __expf(lrelu(h0 * as2 + adv));
        float ex1 = __expf(lrelu(h1 * as2 + adv));
        den += ex0 + ex1;
        num += h0 * ex0 + h1 * ex1;
    }
    if (e < end) {
        float h0 = g_h2[g_esrc[e]];
        float ex0 = __expf(lrelu(h0 * as2 + adv));
        den += ex0;
        num += h0 * ex0;
    }
    out[v] = num / (den + 1e-16f) + b2[0];
}

// ---------------- launch ------------------------------------------------------
extern "C" void kernel_launch(void* const* d_in, const int* in_sizes, int n_in,
                              void* d_out, int out_size) {
    const float* x        = (const float*)d_in[0];
    const void*  ei       = d_in[1];
    const float* W1       = (const float*)d_in[2];
    const float* att_src1 = (const float*)d_in[3];
    const float* att_dst1 = (const float*)d_in[4];
    const float* b1       = (const float*)d_in[5];
    const float* W2       = (const float*)d_in[6];
    const float* att_src2 = (const float*)d_in[7];
    const float* att_dst2 = (const float*)d_in[8];
    const float* b2       = (const float*)d_in[9];
    float* out = (float*)d_out;

    int n = in_sizes[0] / 128;
    int e = in_sizes[1] / 2;
    int tot = e + n;
    int nb = (n + SCAN_BLK - 1) / SCAN_BLK;

    cudaFuncSetAttribute(gemm1_kernel,
                         cudaFuncAttributeMaxDynamicSharedMemorySize, GEMM_SMEM);

    detect_init_kernel<<<64, 256>>>((const unsigned*)ei, e, n, W1);
    hist_kernel<<<(tot + 255) / 256, 256>>>(ei, e, n);
    scan_kernel<<<nb, SCAN_BLK>>>(n, tot);
    scatter_kernel<<<(tot + 255) / 256, 256>>>(ei, e, n);
    gemm1_kernel<<<(n + 127) / 128, 256, GEMM_SMEM>>>(x, att_src1, att_dst1, n);
    agg1_kernel<<<(n + 7) / 8, 256>>>(b1, W2, n);
    agg2_kernel<<<(n + 255) / 256, 256>>>(att_src2, att_dst2, b2, out, n);
}

// round 7
// speedup vs baseline: 2.7463x; 1.0508x over previous
#include <cuda_runtime.h>
#include <cuda_fp16.h>

#define MAXN 100000
#define MAXE 1600000
#define SCAN_BLK 1024

// ---------------- scratch (device globals; no allocations allowed) ----------
__device__ __align__(16) __half2  g_h1h[MAXN * 64];   // h1 fp16, 128 ch/row
__device__ __align__(16) float    g_as1[MAXN * 4];
__device__ __align__(16) float    g_ad1[MAXN * 4];
__device__ float                  g_h2[MAXN];
__device__ int                    g_is64;
__device__ int g_deg[MAXN];
__device__ int g_rowptr[MAXN + 1];
__device__ int g_cursor[MAXN];
__device__ int g_esrc[MAXE];
__device__ unsigned long long g_scanpack[128];        // (flag<<32)|value
// W1 as fp16 hi/lo, stored [n][k] row-major (k contiguous) for mma B operand
__device__ __align__(16) __half g_W1h_hi[128 * 128];
__device__ __align__(16) __half g_W1h_lo[128 * 128];

__device__ __forceinline__ float lrelu(float v) { return v > 0.f ? v : 0.2f * v; }

__device__ __forceinline__ void edge_fetch(const void* ei, int e_cnt, int i,
                                           int is64, int& src, int& dst) {
    if (is64) {
        const long long* p = (const long long*)ei;
        src = (int)p[i];
        dst = (int)p[e_cnt + i];
    } else {
        const int* p = (const int*)ei;
        src = p[i];
        dst = p[e_cnt + i];
    }
}

__device__ __forceinline__ unsigned smem_u32(const void* p) {
    unsigned a;
    asm("{ .reg .u64 t; cvta.to.shared.u64 t, %1; cvt.u32.u64 %0, t; }"
        : "=r"(a) : "l"(p));
    return a;
}

__device__ __forceinline__ void ldsm_x4(unsigned* r, unsigned addr) {
    asm volatile("ldmatrix.sync.aligned.m8n8.x4.shared.b16 {%0,%1,%2,%3}, [%4];"
                 : "=r"(r[0]), "=r"(r[1]), "=r"(r[2]), "=r"(r[3]) : "r"(addr));
}
__device__ __forceinline__ void ldsm_x2(unsigned* r, unsigned addr) {
    asm volatile("ldmatrix.sync.aligned.m8n8.x2.shared.b16 {%0,%1}, [%2];"
                 : "=r"(r[0]), "=r"(r[1]) : "r"(addr));
}
__device__ __forceinline__ void mma16816(float* d, const unsigned* a,
                                         const unsigned* b) {
    asm volatile(
        "mma.sync.aligned.m16n8k16.row.col.f32.f16.f16.f32 "
        "{%0,%1,%2,%3}, {%4,%5,%6,%7}, {%8,%9}, {%0,%1,%2,%3};"
        : "+f"(d[0]), "+f"(d[1]), "+f"(d[2]), "+f"(d[3])
        : "r"(a[0]), "r"(a[1]), "r"(a[2]), "r"(a[3]), "r"(b[0]), "r"(b[1]));
}

// ---------------- init: zero deg + scan flags, detect dtype, convert W ------
__global__ void detect_init_kernel(const unsigned* __restrict__ ei_u32,
                                   int e_cnt, int n,
                                   const float* __restrict__ W) {
    int gid = blockIdx.x * blockDim.x + threadIdx.x;
    int stride = gridDim.x * blockDim.x;
    for (int i = gid; i < n; i += stride) g_deg[i] = 0;
    if (gid < 128) g_scanpack[gid] = 0ull;
    for (int i = gid; i < 128 * 128; i += stride) {
        int k = i >> 7, nn = i & 127;          // W[k][nn] -> B[nn][k]
        float w = W[i];
        __half hi = __float2half_rn(w);
        __half lo = __float2half_rn(w - __half2float(hi));
        g_W1h_hi[nn * 128 + k] = hi;
        g_W1h_lo[nn * 128 + k] = lo;
    }
    if (blockIdx.x == 0) {
        __shared__ int bad;
        if (threadIdx.x == 0) bad = 0;
        __syncthreads();
        int samples = e_cnt < 4096 ? e_cnt : 4096;
        for (int i = threadIdx.x; i < samples; i += blockDim.x)
            if (ei_u32[2 * i + 1] != 0u) bad = 1;
        __syncthreads();
        if (threadIdx.x == 0) g_is64 = bad ? 0 : 1;
    }
}

// ---------------- CSR: single-pass scan (warp shuffles + lookback) ----------
__global__ void scan_kernel(int n, int tot) {
    __shared__ int warpsum[32];
    __shared__ int s_prev;
    int t = threadIdx.x, b = blockIdx.x;
    int i = b * SCAN_BLK + t;
    int lane = t & 31, wid = t >> 5;
    int val = (i < n) ? g_deg[i] : 0;
    int x = val;
#pragma unroll
    for (int o = 1; o < 32; o <<= 1) {
        int y = __shfl_up_sync(0xffffffffu, x, o);
        if (lane >= o) x += y;
    }
    if (lane == 31) warpsum[wid] = x;
    __syncthreads();
    if (wid == 0) {
        int wv = warpsum[lane];
#pragma unroll
        for (int o = 1; o < 32; o <<= 1) {
            int y = __shfl_up_sync(0xffffffffu, wv, o);
            if (lane >= o) wv += y;
        }
        warpsum[lane] = wv;
    }
    __syncthreads();
    int incl = x + (wid ? warpsum[wid - 1] : 0);
    int agg = warpsum[31];

    if (b == 0) {
        if (t == 0) {
            *(volatile unsigned long long*)&g_scanpack[0] =
                (2ull << 32) | (unsigned)agg;
            s_prev = 0;
        }
    } else if (t < 32) {
        if (t == 0)
            *(volatile unsigned long long*)&g_scanpack[b] =
                (1ull << 32) | (unsigned)agg;
        __syncwarp();
        int sum = 0;
        int base = b - 1;
        for (;;) {
            int j = base - lane;
            unsigned long long w;
            unsigned f;
            for (;;) {
                w = (j >= 0) ? *(volatile unsigned long long*)&g_scanpack[j]
                             : (2ull << 32);
                f = (unsigned)(w >> 32);
                if (__all_sync(0xffffffffu, f != 0u)) break;
            }
            unsigned m2 = __ballot_sync(0xffffffffu, f == 2u);
            int fl = m2 ? (__ffs(m2) - 1) : 32;
            int take = (lane <= fl) ? (int)(unsigned)w : 0;
#pragma unroll
            for (int o = 16; o > 0; o >>= 1)
                take += __shfl_xor_sync(0xffffffffu, take, o);
            sum += take;
            if (m2) break;
            base -= 32;
        }
        if (t == 0) {
            *(volatile unsigned long long*)&g_scanpack[b] =
                (2ull << 32) | (unsigned)(sum + agg);
            s_prev = sum;
        }
    }
    __syncthreads();
    int pre = s_prev;
    if (i < n) {
        int r = pre + incl - val;
        g_rowptr[i] = r;
        g_cursor[i] = r;
    }
    if (i == 0) g_rowptr[n] = tot;
}

// ---------------- CSR: scatter (edges only; self-loops analytic) ------------
__global__ void scatter_kernel(const void* __restrict__ ei, int e_cnt) {
    int i = blockIdx.x * blockDim.x + threadIdx.x;
    if (i >= e_cnt) return;
    int is64 = g_is64;
    int src, dst;
    edge_fetch(ei, e_cnt, i, is64, src, dst);
    int pos = atomicAdd(&g_cursor[dst], 1);
    g_esrc[pos] = src;
}

// ---------------- GEMM1 (HMMA split-fp16) + fused histogram + att epilogue --
#define TS 136
#define TILE_B (128 * TS * 2)          // 34816 bytes
#define OFF_AH 0
#define OFF_AL TILE_B
#define OFF_BH (2 * TILE_B)
#define OFF_BL (3 * TILE_B)
#define GEMM_SMEM (4 * TILE_B)         // 139264

__global__ void __launch_bounds__(256, 1)
gemm1_kernel(const float* __restrict__ x,
             const float* __restrict__ att_s,
             const float* __restrict__ att_d, int n,
             const void* __restrict__ ei, int e_cnt) {
    extern __shared__ char smc[];
    unsigned sbase = smem_u32(smc);
    int t = threadIdx.x, lane = t & 31, w = t >> 5;

    // B tiles: copy [n][k] fp16 images into padded smem rows
    {
        const uint4* bh = (const uint4*)g_W1h_hi;
        const uint4* bl = (const uint4*)g_W1h_lo;
#pragma unroll
        for (int i = 0; i < 8; i++) {
            int idx = t + i * 256;         // 0..2047 uint4s (16 per row)
            int row = idx >> 4, c8 = idx & 15;
            *(uint4*)(smc + OFF_BH + row * 272 + c8 * 16) = bh[idx];
            *(uint4*)(smc + OFF_BL + row * 272 + c8 * 16) = bl[idx];
        }
    }

    // A tile: load x fp32, split hi/lo fp16 into padded smem rows
    {
        int m = t >> 1, half = t & 1;
        int row = blockIdx.x * 128 + m;
        const float4* xr = (const float4*)(x + (size_t)row * 128 + half * 64);
#pragma unroll 4
        for (int j = 0; j < 16; j++) {
            float4 v = make_float4(0.f, 0.f, 0.f, 0.f);
            if (row < n) v = xr[j];
            __half h0 = __float2half_rn(v.x), h1 = __float2half_rn(v.y);
            __half h2 = __float2half_rn(v.z), h3 = __float2half_rn(v.w);
            __half l0 = __float2half_rn(v.x - __half2float(h0));
            __half l1 = __float2half_rn(v.y - __half2float(h1));
            __half l2 = __float2half_rn(v.z - __half2float(h2));
            __half l3 = __float2half_rn(v.w - __half2float(h3));
            int k = half * 64 + 4 * j;
            unsigned off = (unsigned)(m * 272 + k * 2);
            __half2 hp0 = __halves2half2(h0, h1), hp1 = __halves2half2(h2, h3);
            __half2 lp0 = __halves2half2(l0, l1), lp1 = __halves2half2(l2, l3);
            uint2 hp, lp;
            hp.x = *(unsigned*)&hp0; hp.y = *(unsigned*)&hp1;
            lp.x = *(unsigned*)&lp0; lp.y = *(unsigned*)&lp1;
            *(uint2*)(smc + OFF_AH + off) = hp;
            *(uint2*)(smc + OFF_AL + off) = lp;
        }
    }

    // Fused CSR histogram (overlaps memory pipes with tensor work below).
    {
        int is64 = g_is64;
        int stride = gridDim.x * blockDim.x;
        if (is64) {
            const long long* p = (const long long*)ei + e_cnt;
            for (int i = blockIdx.x * blockDim.x + t; i < e_cnt; i += stride)
                atomicAdd(&g_deg[(int)p[i]], 1);
        } else {
            const int* p = (const int*)ei + e_cnt;
            for (int i = blockIdx.x * blockDim.x + t; i < e_cnt; i += stride)
                atomicAdd(&g_deg[p[i]], 1);
        }
    }
    __syncthreads();

    int m0 = w * 16;
    float acc[16][4];
#pragma unroll
    for (int nt = 0; nt < 16; nt++)
#pragma unroll
        for (int j = 0; j < 4; j++) acc[nt][j] = 0.f;

    unsigned aBase = sbase + OFF_AH +
        (unsigned)((m0 + (lane & 15)) * 272 + ((lane >> 4) * 8) * 2);
    unsigned bRow  = (unsigned)(lane & 7);
    unsigned bKoff = (unsigned)(((lane >> 3) & 1) * 8);

    for (int kt = 0; kt < 8; kt++) {
        unsigned aA = aBase + kt * 32;
        unsigned ah[4], al[4];
        ldsm_x4(ah, aA);
        ldsm_x4(al, aA + TILE_B);
#pragma unroll
        for (int nt = 0; nt < 16; nt++) {
            unsigned bAddr = sbase + OFF_BH +
                (unsigned)((nt * 8 + bRow) * 272 + (kt * 16 + bKoff) * 2);
            unsigned bh[2], bl[2];
            ldsm_x2(bh, bAddr);
            ldsm_x2(bl, bAddr + TILE_B);
            mma16816(acc[nt], ah, bh);
            mma16816(acc[nt], ah, bl);
            mma16816(acc[nt], al, bh);
        }
    }

    // Epilogue: thread holds rows r0 = m0+lane/4, r1 = r0+8,
    // cols n = nt*8 + 2*(lane%4) + {0,1}. Store fp16 h1 + head reductions.
    {
        int gr = lane >> 2, c = lane & 3;
        int r0 = blockIdx.x * 128 + m0 + gr;
        int r1 = r0 + 8;
        float sv0[4] = {0, 0, 0, 0}, dv0[4] = {0, 0, 0, 0};
        float sv1[4] = {0, 0, 0, 0}, dv1[4] = {0, 0, 0, 0};
#pragma unroll
        for (int nt = 0; nt < 16; nt++) {
            int col = nt * 8 + 2 * c;
            float w0 = att_s[col], w1 = att_s[col + 1];
            float u0 = att_d[col], u1 = att_d[col + 1];
            int hd = nt >> 2;
            sv0[hd] += acc[nt][0] * w0 + acc[nt][1] * w1;
            dv0[hd] += acc[nt][0] * u0 + acc[nt][1] * u1;
            sv1[hd] += acc[nt][2] * w0 + acc[nt][3] * w1;
            dv1[hd] += acc[nt][2] * u0 + acc[nt][3] * u1;
            if (r0 < n)
                g_h1h[(size_t)r0 * 64 + nt * 4 + c] =
                    __floats2half2_rn(acc[nt][0], acc[nt][1]);
            if (r1 < n)
                g_h1h[(size_t)r1 * 64 + nt * 4 + c] =
                    __floats2half2_rn(acc[nt][2], acc[nt][3]);
        }
#pragma unroll
        for (int hd = 0; hd < 4; hd++) {
#pragma unroll
            for (int o = 1; o < 4; o <<= 1) {
                sv0[hd] += __shfl_xor_sync(0xffffffffu, sv0[hd], o);
                dv0[hd] += __shfl_xor_sync(0xffffffffu, dv0[hd], o);
                sv1[hd] += __shfl_xor_sync(0xffffffffu, sv1[hd], o);
                dv1[hd] += __shfl_xor_sync(0xffffffffu, dv1[hd], o);
            }
        }
        if (c == 0) {
#pragma unroll
            for (int hd = 0; hd < 4; hd++) {
                if (r0 < n) {
                    g_as1[r0 * 4 + hd] = sv0[hd];
                    g_ad1[r0 * 4 + hd] = dv0[hd];
                }
                if (r1 < n) {
                    g_as1[r1 * 4 + hd] = sv1[hd];
                    g_ad1[r1 * 4 + hd] = dv1[hd];
                }
            }
        }
    }
}

// ---------------- layer-1 aggregation (CSR, warp per dst; self-loop fused) --
__global__ void agg1_kernel(const float* __restrict__ b1,
                            const float* __restrict__ W2, int n) {
    int v = (blockIdx.x * blockDim.x + threadIdx.x) >> 5;
    int lane = threadIdx.x & 31;
    if (v >= n) return;
    int hd = lane >> 3;
    int beg = g_rowptr[v];
    int end = g_rowptr[v + 1];
    float adv = g_ad1[v * 4 + hd];
    const uint2* H2 = (const uint2*)g_h1h;

    // self-loop contribution (exact: loops were excluded from the CSR)
    float4 acc;
    float den;
    {
        float exs = __expf(lrelu(g_as1[v * 4 + hd] + adv));
        uint2 pv = H2[v * 32 + lane];
        float2 q0 = __half22float2(*(__half2*)&pv.x);
        float2 q1 = __half22float2(*(__half2*)&pv.y);
        den = exs;
        acc = make_float4(q0.x * exs, q0.y * exs, q1.x * exs, q1.y * exs);
    }

    int e = beg;
    for (; e + 3 < end; e += 4) {
        int s0 = g_esrc[e], s1 = g_esrc[e + 1];
        int s2 = g_esrc[e + 2], s3 = g_esrc[e + 3];
        float a0 = g_as1[s0 * 4 + hd], a1 = g_as1[s1 * 4 + hd];
        float a2 = g_as1[s2 * 4 + hd], a3 = g_as1[s3 * 4 + hd];
        uint2 p0 = H2[s0 * 32 + lane], p1 = H2[s1 * 32 + lane];
        uint2 p2 = H2[s2 * 32 + lane], p3 = H2[s3 * 32 + lane];
        float e0 = __expf(lrelu(a0 + adv)), e1 = __expf(lrelu(a1 + adv));
        float e2 = __expf(lrelu(a2 + adv)), e3 = __expf(lrelu(a3 + adv));
        den += (e0 + e1) + (e2 + e3);
        float2 q;
        q = __half22float2(*(__half2*)&p0.x); acc.x += q.x * e0; acc.y += q.y * e0;
        q = __half22float2(*(__half2*)&p0.y); acc.z += q.x * e0; acc.w += q.y * e0;
        q = __half22float2(*(__half2*)&p1.x); acc.x += q.x * e1; acc.y += q.y * e1;
        q = __half22float2(*(__half2*)&p1.y); acc.z += q.x * e1; acc.w += q.y * e1;
        q = __half22float2(*(__half2*)&p2.x); acc.x += q.x * e2; acc.y += q.y * e2;
        q = __half22float2(*(__half2*)&p2.y); acc.z += q.x * e2; acc.w += q.y * e2;
        q = __half22float2(*(__half2*)&p3.x); acc.x += q.x * e3; acc.y += q.y * e3;
        q = __half22float2(*(__half2*)&p3.y); acc.z += q.x * e3; acc.w += q.y * e3;
    }
    for (; e < end; e++) {
        int s0 = g_esrc[e];
        float e0 = __expf(lrelu(g_as1[s0 * 4 + hd] + adv));
        uint2 p0 = H2[s0 * 32 + lane];
        float2 q;
        den += e0;
        q = __half22float2(*(__half2*)&p0.x); acc.x += q.x * e0; acc.y += q.y * e0;
        q = __half22float2(*(__half2*)&p0.y); acc.z += q.x * e0; acc.w += q.y * e0;
    }

    float inv = 1.f / (den + 1e-16f);
    float4 bb = ((const float4*)b1)[lane];
    float4 w  = ((const float4*)W2)[lane];
    float x0 = fmaxf(acc.x * inv + bb.x, 0.f);
    float x1 = fmaxf(acc.y * inv + bb.y, 0.f);
    float x2 = fmaxf(acc.z * inv + bb.z, 0.f);
    float x3 = fmaxf(acc.w * inv + bb.w, 0.f);
    float s = x0 * w.x + x1 * w.y + x2 * w.z + x3 * w.w;
#pragma unroll
    for (int o = 16; o > 0; o >>= 1) s += __shfl_xor_sync(0xffffffffu, s, o);
    if (lane == 0) g_h2[v] = s;
}

// ---------------- layer-2 aggregation (CSR, thread per dst; self-loop fused) -
__global__ void agg2_kernel(const float* __restrict__ att_s2,
                            const float* __restrict__ att_d2,
                            const float* __restrict__ b2,
                            float* __restrict__ out, int n) {
    int v = blockIdx.x * blockDim.x + threadIdx.x;
    if (v >= n) return;
    float as2 = att_s2[0];
    float hv = g_h2[v];
    float adv = hv * att_d2[0];
    int beg = g_rowptr[v];
    int end = g_rowptr[v + 1];
    float exs = __expf(lrelu(hv * as2 + adv));
    float den = exs, num = hv * exs;
    int e = beg;
    for (; e + 3 < end; e += 4) {
        int s0 = g_esrc[e], s1 = g_esrc[e + 1];
        int s2 = g_esrc[e + 2], s3 = g_esrc[e + 3];
        float h0 = g_h2[s0], h1 = g_h2[s1], h2 = g_h2[s2], h3 = g_h2[s3];
        float e0 = __expf(lrelu(h0 * as2 + adv));
        float e1 = __expf(lrelu(h1 * as2 + adv));
        float e2 = __expf(lrelu(h2 * as2 + adv));
        float e3 = __expf(lrelu(h3 * as2 + adv));
        den += (e0 + e1) + (e2 + e3);
        num += (h0 * e0 + h1 * e1) + (h2 * e2 + h3 * e3);
    }
    for (; e < end; e++) {
        float h0 = g_h2[g_esrc[e]];
        float e0 = __expf(lrelu(h0 * as2 + adv));
        den += e0;
        num += h0 * e0;
    }
    out[v] = num / (den + 1e-16f) + b2[0];
}

// ---------------- launch ------------------------------------------------------
extern "C" void kernel_launch(void* const* d_in, const int* in_sizes, int n_in,
                              void* d_out, int out_size) {
    const float* x        = (const float*)d_in[0];
    const void*  ei       = d_in[1];
    const float* W1       = (const float*)d_in[2];
    const float* att_src1 = (const float*)d_in[3];
    const float* att_dst1 = (const float*)d_in[4];
    const float* b1       = (const float*)d_in[5];
    const float* W2       = (const float*)d_in[6];
    const float* att_src2 = (const float*)d_in[7];
    const float* att_dst2 = (const float*)d_in[8];
    const float* b2       = (const float*)d_in[9];
    float* out = (float*)d_out;

    int n = in_sizes[0] / 128;
    int e = in_sizes[1] / 2;
    int nb = (n + SCAN_BLK - 1) / SCAN_BLK;

    cudaFuncSetAttribute(gemm1_kernel,
                         cudaFuncAttributeMaxDynamicSharedMemorySize, GEMM_SMEM);

    detect_init_kernel<<<64, 256>>>((const unsigned*)ei, e, n, W1);
    gemm1_kernel<<<(n + 127) / 128, 256, GEMM_SMEM>>>(x, att_src1, att_dst1, n,
                                                      ei, e);
    scan_kernel<<<nb, SCAN_BLK>>>(n, e);
    scatter_kernel<<<(e + 255) / 256, 256>>>(ei, e);
    agg1_kernel<<<(n + 7) / 8, 256>>>(b1, W2, n);
    agg2_kernel<<<(n + 255) / 256, 256>>>(att_src2, att_dst2, b2, out, n);
}